// round 14
// baseline (speedup 1.0000x reference)
#include <cuda_runtime.h>
#include <cuda_fp16.h>
#include <stdint.h>

// ---------------- Problem constants (fixed dataset) ----------------
#define NMAX 100000
#define EMAX 1600000
#define DIM_IN  512
#define DIM_HID 128
#define DIM_OUT 64

#define SCAN_BLK 1024

// ---------------- Device scratch (no allocations allowed) ----------------
__device__ float g_bufA[(size_t)NMAX * DIM_HID];   // gemm outputs (fp16 stored)
__device__ float g_bufB[(size_t)NMAX * DIM_HID];   // spmm outputs (fp16 stored)
__device__ int   g_deg[NMAX];
__device__ int   g_rowptr[NMAX + 1];
__device__ int   g_rowptr2[NMAX];                  // mutable copy for scatter
__device__ int   g_blksum[128];
__device__ int2  g_epack[EMAX];                    // (col, val bits) per CSR slot

// ---------------- helpers ----------------
__device__ __forceinline__ uint32_t smem_u32(const void* p) {
    uint32_t a;
    asm("{ .reg .u64 t; cvta.to.shared.u64 t, %1; cvt.u32.u64 %0, t; }" : "=r"(a) : "l"(p));
    return a;
}
__device__ __forceinline__ uint32_t sw128(uint32_t b) { return b ^ ((b >> 3) & 0x70); }

__device__ __forceinline__ void ldsm_x4(uint32_t* r, uint32_t addr) {
    asm volatile("ldmatrix.sync.aligned.m8n8.x4.shared.b16 {%0,%1,%2,%3}, [%4];"
                 : "=r"(r[0]), "=r"(r[1]), "=r"(r[2]), "=r"(r[3]) : "r"(addr));
}
// fp16 MMA, fp32 accumulate
__device__ __forceinline__ void mma16816(float* d, const uint32_t* a, const uint32_t* b) {
    asm volatile(
        "mma.sync.aligned.m16n8k16.row.col.f32.f16.f16.f32 "
        "{%0,%1,%2,%3}, {%4,%5,%6,%7}, {%8,%9}, {%0,%1,%2,%3};"
        : "+f"(d[0]), "+f"(d[1]), "+f"(d[2]), "+f"(d[3])
        : "r"(a[0]), "r"(a[1]), "r"(a[2]), "r"(a[3]), "r"(b[0]), "r"(b[1]));
}

__device__ __forceinline__ uint2 cvt_hi(float4 v) {
    __half2 h01 = __floats2half2_rn(v.x, v.y);
    __half2 h23 = __floats2half2_rn(v.z, v.w);
    return make_uint2(*(uint32_t*)&h01, *(uint32_t*)&h23);
}
__device__ __forceinline__ uint2 cvt_lo(float4 v, uint2 hi) {
    float2 f01 = __half22float2(*(__half2*)&hi.x);
    float2 f23 = __half22float2(*(__half2*)&hi.y);
    __half2 l01 = __floats2half2_rn(v.x - f01.x, v.y - f01.y);
    __half2 l23 = __floats2half2_rn(v.z - f23.x, v.w - f23.y);
    return make_uint2(*(uint32_t*)&l01, *(uint32_t*)&l23);
}

// ---------------- CSR build ----------------
__global__ void zero_deg_kernel(int n) {
    int i = blockIdx.x * blockDim.x + threadIdx.x;
    if (i < n) g_deg[i] = 0;
}

__global__ void hist_kernel(const int* __restrict__ rows, int E) {
    int i = blockIdx.x * blockDim.x + threadIdx.x;
    if (i < E) atomicAdd(&g_deg[rows[i]], 1);
}

__global__ void scan_blocks_kernel(int n) {
    __shared__ int warpsums[32];
    int tid = threadIdx.x, lane = tid & 31, wid = tid >> 5;
    int i = blockIdx.x * SCAN_BLK + tid;
    int v = (i < n) ? g_deg[i] : 0;
    int x = v;
    #pragma unroll
    for (int o = 1; o < 32; o <<= 1) {
        int y = __shfl_up_sync(0xffffffffu, x, o);
        if (lane >= o) x += y;
    }
    if (lane == 31) warpsums[wid] = x;
    __syncthreads();
    if (wid == 0) {
        int s = warpsums[lane];
        #pragma unroll
        for (int o = 1; o < 32; o <<= 1) {
            int y = __shfl_up_sync(0xffffffffu, s, o);
            if (lane >= o) s += y;
        }
        warpsums[lane] = s;
    }
    __syncthreads();
    int pref = (wid > 0) ? warpsums[wid - 1] : 0;
    int incl = x + pref;
    if (i < n) g_rowptr[i] = incl - v;
    if (tid == SCAN_BLK - 1) g_blksum[blockIdx.x] = incl;
}

// Fused offset-add: each block reduces blksum[j < blockIdx] itself (98 ints),
// adds to its rowptr slice, materializes scatter cursor copy; last block
// writes the grand total.
__global__ void scan_add_kernel(int nb, int n) {
    __shared__ int s_sums[128];
    __shared__ int s_off[2];          // [0] = my offset, [1] = grand total
    int tid = threadIdx.x;
    if (tid < nb) s_sums[tid] = g_blksum[tid];
    __syncthreads();
    if (tid == 0) {
        int off = 0, tot = 0;
        for (int j = 0; j < nb; j++) {
            if (j < (int)blockIdx.x) off += s_sums[j];
            tot += s_sums[j];
        }
        s_off[0] = off;
        s_off[1] = tot;
    }
    __syncthreads();
    int i = blockIdx.x * SCAN_BLK + tid;
    if (i < n) {
        int v = g_rowptr[i] + s_off[0];
        g_rowptr[i]  = v;
        g_rowptr2[i] = v;
    }
    if (blockIdx.x == (unsigned)(nb - 1) && tid == 0)
        g_rowptr[n] = s_off[1];
}

// Single atomic per edge: cursor atomicAdd yields the slot directly.
__global__ void scatter_kernel(const int* __restrict__ rows,
                               const int* __restrict__ cols,
                               const float* __restrict__ vals, int E) {
    int i = blockIdx.x * blockDim.x + threadIdx.x;
    if (i < E) {
        int p = atomicAdd(&g_rowptr2[rows[i]], 1);
        g_epack[p] = make_int2(cols[i], __float_as_int(vals[i]));
    }
}

// ---------------- Tensor-core GEMM via fp16 mma.sync ----------------
// C[M,BN] = A[M,K] * W[BN,K]^T.
// TERMS=2: D += Ah*Bh + Ah*Bl (W split hi/lo).  TERMS=1: D += Ah*Bh.
// AHALF: A already fp16 (smem fill is a straight copy).
// K-chunk = 64 -> 128B fp16 rows, SW128 swizzle, double-buffered. fp16 out.
template <int BM, int BN, int WM, int WN, int K, bool AHALF, int TERMS>
__global__ void __launch_bounds__(WM * WN * 32, 2)
mma_gemm_kernel(const void* __restrict__ Av, const float* __restrict__ W,
                __half* __restrict__ C, int M)
{
    constexpr int THREADS = WM * WN * 32;
    constexpr int NCHUNK  = K / 64;
    constexpr int ASZ = BM * 128;
    constexpr int BSZ = BN * 128;
    constexpr int BUF = ASZ + TERMS * BSZ;
    constexpr int ALF = BM * 16 / THREADS;
    constexpr int ALH = BM * 8 / THREADS;
    constexpr int BL  = BN * 16 / THREADS;
    constexpr int MT  = BM / WM / 16;
    constexpr int NT  = BN / WN / 8;

    extern __shared__ __align__(1024) char smem[];
    const uint32_t sb = smem_u32(smem);

    const int tid = threadIdx.x;
    const int l   = tid & 31;
    const int w   = tid >> 5;
    const int wmBase = (w % WM) * (BM / WM);
    const int wnBase = (w / WM) * (BN / WN);
    const int m0 = blockIdx.x * BM;

    const float*  Af = (const float*)Av;
    const __half* Ah = (const __half*)Av;

    float acc[MT][NT][4];
    #pragma unroll
    for (int i = 0; i < MT; i++)
        #pragma unroll
        for (int j = 0; j < NT; j++)
            #pragma unroll
            for (int q = 0; q < 4; q++) acc[i][j][q] = 0.f;

    uint2 regAh[AHALF ? 1 : ALF];
    uint4 regAp[AHALF ? ALH : 1];
    uint2 regBh[BL], regBl[(TERMS == 2) ? BL : 1];

    const int arow = l & 15;
    const int acol = (l & 16) ? 16 : 0;
    const int brow = ((l & 16) ? 8 : 0) + (l & 7);
    const int bcol = (l & 8) ? 16 : 0;

    auto loadChunk = [&](int c) {
        const int k0 = c * 64;
        if constexpr (AHALF) {
            #pragma unroll
            for (int i = 0; i < ALH; i++) {
                int idx = tid + i * THREADS;
                int r = idx >> 3, u = idx & 7;
                int row = m0 + r; if (row >= M) row = M - 1;
                regAp[i] = __ldg((const uint4*)(Ah + (size_t)row * K + k0) + u);
            }
        } else {
            #pragma unroll
            for (int i = 0; i < ALF; i++) {
                int idx = tid + i * THREADS;
                int r = idx >> 4, c4 = (idx & 15) << 2;
                int row = m0 + r; if (row >= M) row = M - 1;
                float4 v = __ldg((const float4*)(Af + (size_t)row * K + k0 + c4));
                regAh[i] = cvt_hi(v);
            }
        }
        #pragma unroll
        for (int i = 0; i < BL; i++) {
            int idx = tid + i * THREADS;
            int r = idx >> 4, c4 = (idx & 15) << 2;
            float4 v = __ldg((const float4*)(W + (size_t)r * K + k0 + c4));
            regBh[i] = cvt_hi(v);
            if constexpr (TERMS == 2) regBl[i] = cvt_lo(v, regBh[i]);
        }
    };

    auto stsChunk = [&](int b) {
        char* base = smem + b * BUF;
        char* aHi  = base;
        char* bHi  = base + ASZ;
        char* bLo  = bHi + BSZ;
        if constexpr (AHALF) {
            #pragma unroll
            for (int i = 0; i < ALH; i++) {
                int idx = tid + i * THREADS;
                int r = idx >> 3, u = idx & 7;
                *(uint4*)(aHi + sw128((uint32_t)(r * 128 + u * 16))) = regAp[i];
            }
        } else {
            #pragma unroll
            for (int i = 0; i < ALF; i++) {
                int idx = tid + i * THREADS;
                int r = idx >> 4, c4 = (idx & 15) << 2;
                *(uint2*)(aHi + sw128((uint32_t)(r * 128 + c4 * 2))) = regAh[i];
            }
        }
        #pragma unroll
        for (int i = 0; i < BL; i++) {
            int idx = tid + i * THREADS;
            int r = idx >> 4, c4 = (idx & 15) << 2;
            uint32_t off = sw128((uint32_t)(r * 128 + c4 * 2));
            *(uint2*)(bHi + off) = regBh[i];
            if constexpr (TERMS == 2) *(uint2*)(bLo + off) = regBl[i];
        }
    };

    auto compute = [&](int b) {
        const uint32_t sAhi = sb + b * BUF;
        const uint32_t sBhi = sAhi + ASZ;
        const uint32_t sBlo = sBhi + BSZ;
        #pragma unroll
        for (int kb = 0; kb < 4; kb++) {
            const int kboff = kb * 32;
            uint32_t aH[MT][4];
            #pragma unroll
            for (int mt = 0; mt < MT; mt++) {
                uint32_t rowb = (uint32_t)((wmBase + mt * 16 + arow) * 128);
                ldsm_x4(aH[mt], sAhi + sw128(rowb + kboff + acol));
            }
            uint32_t bH[NT][2], bLo[NT][2];
            #pragma unroll
            for (int nt = 0; nt < NT; nt += 2) {
                uint32_t rowb = (uint32_t)((wnBase + nt * 8 + brow) * 128);
                uint32_t t[4];
                ldsm_x4(t, sBhi + sw128(rowb + kboff + bcol));
                bH[nt][0] = t[0]; bH[nt][1] = t[1];
                bH[nt + 1][0] = t[2]; bH[nt + 1][1] = t[3];
                if constexpr (TERMS == 2) {
                    ldsm_x4(t, sBlo + sw128(rowb + kboff + bcol));
                    bLo[nt][0] = t[0]; bLo[nt][1] = t[1];
                    bLo[nt + 1][0] = t[2]; bLo[nt + 1][1] = t[3];
                }
            }
            #pragma unroll
            for (int mt = 0; mt < MT; mt++)
                #pragma unroll
                for (int nt = 0; nt < NT; nt++) {
                    mma16816(acc[mt][nt], aH[mt], bH[nt]);
                    if constexpr (TERMS == 2)
                        mma16816(acc[mt][nt], aH[mt], bLo[nt]);
                }
        }
    };

    loadChunk(0);
    stsChunk(0);
    __syncthreads();

    for (int c = 0; c < NCHUNK; c++) {
        if (c + 1 < NCHUNK) loadChunk(c + 1);
        compute(c & 1);
        if (c + 1 < NCHUNK) {
            __syncthreads();
            stsChunk((c + 1) & 1);
            __syncthreads();
        }
    }

    #pragma unroll
    for (int mt = 0; mt < MT; mt++) {
        int m = m0 + wmBase + mt * 16 + (l >> 2);
        #pragma unroll
        for (int nt = 0; nt < NT; nt++) {
            int nn = wnBase + nt * 8 + ((l & 3) << 1);
            if (m < M)
                *(__half2*)(C + (size_t)m * BN + nn) =
                    __floats2half2_rn(acc[mt][nt][0], acc[mt][nt][1]);
            if (m + 8 < M)
                *(__half2*)(C + (size_t)(m + 8) * BN + nn) =
                    __floats2half2_rn(acc[mt][nt][2], acc[mt][nt][3]);
        }
    }
}

// ---------------- SpMM (CSR, warp per row, fp16 gather, 2x unroll) ---------
// h fp16, accumulate fp32. OUTHALF: store fp16, else fp32.
template <int WIDTH, bool RELU, bool OUTHALF>
__global__ void spmm_kernel(const __half* __restrict__ h,
                            void* __restrict__ outv, int n) {
    int warp = (blockIdx.x * blockDim.x + threadIdx.x) >> 5;
    int lane = threadIdx.x & 31;
    if (warp >= n) return;
    int s = g_rowptr[warp];
    int e = g_rowptr[warp + 1];

    if (WIDTH == 128) {
        float4 acc = make_float4(0.f, 0.f, 0.f, 0.f);
        int i = s;
        for (; i + 2 <= e; i += 2) {
            int2 p0 = g_epack[i];
            int2 p1 = g_epack[i + 1];
            float v0 = __int_as_float(p0.y);
            float v1 = __int_as_float(p1.y);
            uint2 r0 = __ldg((const uint2*)(h + (size_t)p0.x * 128) + lane);
            uint2 r1 = __ldg((const uint2*)(h + (size_t)p1.x * 128) + lane);
            float2 a01 = __half22float2(*(__half2*)&r0.x);
            float2 a23 = __half22float2(*(__half2*)&r0.y);
            float2 b01 = __half22float2(*(__half2*)&r1.x);
            float2 b23 = __half22float2(*(__half2*)&r1.y);
            acc.x += v0 * a01.x; acc.y += v0 * a01.y;
            acc.z += v0 * a23.x; acc.w += v0 * a23.y;
            acc.x += v1 * b01.x; acc.y += v1 * b01.y;
            acc.z += v1 * b23.x; acc.w += v1 * b23.y;
        }
        if (i < e) {
            int2 p = g_epack[i];
            float v = __int_as_float(p.y);
            uint2 r0 = __ldg((const uint2*)(h + (size_t)p.x * 128) + lane);
            float2 a01 = __half22float2(*(__half2*)&r0.x);
            float2 a23 = __half22float2(*(__half2*)&r0.y);
            acc.x += v * a01.x; acc.y += v * a01.y;
            acc.z += v * a23.x; acc.w += v * a23.y;
        }
        if (RELU) {
            acc.x = fmaxf(acc.x, 0.f); acc.y = fmaxf(acc.y, 0.f);
            acc.z = fmaxf(acc.z, 0.f); acc.w = fmaxf(acc.w, 0.f);
        }
        if constexpr (OUTHALF) {
            __half2 o01 = __floats2half2_rn(acc.x, acc.y);
            __half2 o23 = __floats2half2_rn(acc.z, acc.w);
            ((uint2*)((__half*)outv + (size_t)warp * 128))[lane] =
                make_uint2(*(uint32_t*)&o01, *(uint32_t*)&o23);
        } else {
            ((float4*)((float*)outv + (size_t)warp * 128))[lane] = acc;
        }
    } else {  // WIDTH == 64
        float2 acc = make_float2(0.f, 0.f);
        int i = s;
        for (; i + 2 <= e; i += 2) {
            int2 p0 = g_epack[i];
            int2 p1 = g_epack[i + 1];
            float v0 = __int_as_float(p0.y);
            float v1 = __int_as_float(p1.y);
            uint32_t r0 = __ldg((const uint32_t*)(h + (size_t)p0.x * 64) + lane);
            uint32_t r1 = __ldg((const uint32_t*)(h + (size_t)p1.x * 64) + lane);
            float2 a = __half22float2(*(__half2*)&r0);
            float2 b = __half22float2(*(__half2*)&r1);
            acc.x += v0 * a.x; acc.y += v0 * a.y;
            acc.x += v1 * b.x; acc.y += v1 * b.y;
        }
        if (i < e) {
            int2 p = g_epack[i];
            float v = __int_as_float(p.y);
            uint32_t r0 = __ldg((const uint32_t*)(h + (size_t)p.x * 64) + lane);
            float2 a = __half22float2(*(__half2*)&r0);
            acc.x += v * a.x; acc.y += v * a.y;
        }
        if (RELU) { acc.x = fmaxf(acc.x, 0.f); acc.y = fmaxf(acc.y, 0.f); }
        ((float2*)((float*)outv + (size_t)warp * 64))[lane] = acc;
    }
}

// ---------------- Launcher ----------------
extern "C" void kernel_launch(void* const* d_in, const int* in_sizes, int n_in,
                              void* d_out, int out_size) {
    const float* x    = (const float*)d_in[0];
    const int*   rows = (const int*)  d_in[1];
    const int*   cols = (const int*)  d_in[2];
    const float* vals = (const float*)d_in[3];
    const float* W0   = (const float*)d_in[4];
    const float* W1   = (const float*)d_in[5];
    const float* W2   = (const float*)d_in[6];
    float* out = (float*)d_out;

    int n = in_sizes[0] / DIM_IN;   // 100000
    int E = in_sizes[1];            // 1600000
    int nb = (n + SCAN_BLK - 1) / SCAN_BLK;

    float* bufA; float* bufB;
    cudaGetSymbolAddress((void**)&bufA, g_bufA);
    cudaGetSymbolAddress((void**)&bufB, g_bufB);
    __half* bufAh = (__half*)bufA;
    __half* bufBh = (__half*)bufB;

    // smem: GEMM0 (TERMS=1, BN=128): 2*(16K+16K)=64K;
    //       GEMM1 (TERMS=2, BN=128): 2*(16K+32K)=96K;
    //       GEMM2 (TERMS=2, BN=64):  2*(16K+16K)=64K.
    const int smemG0 = 2 * 32 * 1024;
    const int smemG1 = 2 * 48 * 1024;
    const int smemG2 = 2 * 32 * 1024;
    cudaFuncSetAttribute(mma_gemm_kernel<128, 128, 2, 4, 512, false, 1>,
                         cudaFuncAttributeMaxDynamicSharedMemorySize, smemG0);
    cudaFuncSetAttribute(mma_gemm_kernel<128, 128, 2, 4, 128, true, 2>,
                         cudaFuncAttributeMaxDynamicSharedMemorySize, smemG1);
    cudaFuncSetAttribute(mma_gemm_kernel<128, 64, 4, 2, 128, true, 2>,
                         cudaFuncAttributeMaxDynamicSharedMemorySize, smemG2);

    // ---- CSR build (5 kernels) ----
    zero_deg_kernel<<<(n + 255) / 256, 256>>>(n);
    hist_kernel<<<(E + 255) / 256, 256>>>(rows, E);
    scan_blocks_kernel<<<nb, SCAN_BLK>>>(n);
    scan_add_kernel<<<nb, SCAN_BLK>>>(nb, n);
    scatter_kernel<<<(E + 255) / 256, 256>>>(rows, cols, vals, E);

    int gemmGrid = (n + 127) / 128;
    int spmmGrid = (n + 7) / 8;

    // layer 0: x(fp32) @ W0^T (1-term) -> fp16; spmm fp16->fp16 + relu
    mma_gemm_kernel<128, 128, 2, 4, 512, false, 1><<<gemmGrid, 256, smemG0>>>(
        x, W0, bufAh, n);
    spmm_kernel<128, true, true><<<spmmGrid, 256>>>(bufAh, bufBh, n);

    // layer 1: h(fp16) @ W1^T (2-term) -> fp16; spmm fp16->fp16 + relu
    mma_gemm_kernel<128, 128, 2, 4, 128, true, 2><<<gemmGrid, 256, smemG1>>>(
        bufBh, W1, bufAh, n);
    spmm_kernel<128, true, true><<<spmmGrid, 256>>>(bufAh, bufBh, n);

    // layer 2: h(fp16) @ W2^T (2-term) -> fp16; spmm fp16->fp32 (no relu)
    mma_gemm_kernel<128, 64, 4, 2, 128, true, 2><<<gemmGrid, 256, smemG2>>>(
        bufBh, W2, bufAh, n);
    spmm_kernel<64, false, false><<<spmmGrid, 256>>>(bufAh, out, n);
}

// round 15
// speedup vs baseline: 1.2684x; 1.2684x over previous
#include <cuda_runtime.h>
#include <cuda_fp16.h>
#include <stdint.h>

// ---------------- Problem constants (fixed dataset) ----------------
#define NMAX 100000
#define EMAX 1600000
#define DIM_IN  512
#define DIM_HID 128
#define DIM_OUT 64

#define SCAN_BLK 1024
#define W1_ELEMS (DIM_HID * DIM_HID)   // 16384
#define W2_ELEMS (DIM_OUT * DIM_HID)   // 8192
#define W12_TOTAL (W1_ELEMS + W2_ELEMS)

// ---------------- Device scratch (no allocations allowed) ----------------
__device__ float g_bufA[(size_t)NMAX * DIM_HID];   // gemm outputs (fp16 stored)
__device__ float g_bufB[(size_t)NMAX * DIM_HID];   // spmm outputs (fp16 stored)
__device__ int   g_deg[NMAX];
__device__ int   g_rowptr[NMAX + 1];
__device__ int   g_rowptr2[NMAX];                  // mutable copy for scatter
__device__ int   g_blksum[128];
__device__ int2  g_epack[EMAX];                    // (col, val bits) per CSR slot
__device__ __half g_Whi[W12_TOTAL];                // W1|W2 fp16 hi plane
__device__ __half g_Wlo[W12_TOTAL];                // W1|W2 fp16 lo plane

// ---------------- helpers ----------------
__device__ __forceinline__ uint32_t smem_u32(const void* p) {
    uint32_t a;
    asm("{ .reg .u64 t; cvta.to.shared.u64 t, %1; cvt.u32.u64 %0, t; }" : "=r"(a) : "l"(p));
    return a;
}
__device__ __forceinline__ uint32_t sw128(uint32_t b) { return b ^ ((b >> 3) & 0x70); }

__device__ __forceinline__ void ldsm_x4(uint32_t* r, uint32_t addr) {
    asm volatile("ldmatrix.sync.aligned.m8n8.x4.shared.b16 {%0,%1,%2,%3}, [%4];"
                 : "=r"(r[0]), "=r"(r[1]), "=r"(r[2]), "=r"(r[3]) : "r"(addr));
}
// fp16 MMA, fp32 accumulate
__device__ __forceinline__ void mma16816(float* d, const uint32_t* a, const uint32_t* b) {
    asm volatile(
        "mma.sync.aligned.m16n8k16.row.col.f32.f16.f16.f32 "
        "{%0,%1,%2,%3}, {%4,%5,%6,%7}, {%8,%9}, {%0,%1,%2,%3};"
        : "+f"(d[0]), "+f"(d[1]), "+f"(d[2]), "+f"(d[3])
        : "r"(a[0]), "r"(a[1]), "r"(a[2]), "r"(a[3]), "r"(b[0]), "r"(b[1]));
}

__device__ __forceinline__ uint2 cvt_hi(float4 v) {
    __half2 h01 = __floats2half2_rn(v.x, v.y);
    __half2 h23 = __floats2half2_rn(v.z, v.w);
    return make_uint2(*(uint32_t*)&h01, *(uint32_t*)&h23);
}
__device__ __forceinline__ uint2 cvt_lo(float4 v, uint2 hi) {
    float2 f01 = __half22float2(*(__half2*)&hi.x);
    float2 f23 = __half22float2(*(__half2*)&hi.y);
    __half2 l01 = __floats2half2_rn(v.x - f01.x, v.y - f01.y);
    __half2 l23 = __floats2half2_rn(v.z - f23.x, v.w - f23.y);
    return make_uint2(*(uint32_t*)&l01, *(uint32_t*)&l23);
}

// ---------------- W1/W2 pre-split (tiny, once per launch) ----------------
__global__ void convert_w_kernel(const float* __restrict__ W1,
                                 const float* __restrict__ W2) {
    int i = blockIdx.x * blockDim.x + threadIdx.x;
    if (i >= W12_TOTAL) return;
    float v = (i < W1_ELEMS) ? W1[i] : W2[i - W1_ELEMS];
    __half h = __float2half_rn(v);
    g_Whi[i] = h;
    g_Wlo[i] = __float2half_rn(v - __half2float(h));
}

// ---------------- CSR build ----------------
__global__ void zero_deg_kernel(int n) {
    int i = blockIdx.x * blockDim.x + threadIdx.x;
    if (i < n) g_deg[i] = 0;
}

__global__ void hist_kernel(const int* __restrict__ rows, int E) {
    int i = blockIdx.x * blockDim.x + threadIdx.x;
    if (i < E) atomicAdd(&g_deg[rows[i]], 1);
}

__global__ void scan_blocks_kernel(int n) {
    __shared__ int warpsums[32];
    int tid = threadIdx.x, lane = tid & 31, wid = tid >> 5;
    int i = blockIdx.x * SCAN_BLK + tid;
    int v = (i < n) ? g_deg[i] : 0;
    int x = v;
    #pragma unroll
    for (int o = 1; o < 32; o <<= 1) {
        int y = __shfl_up_sync(0xffffffffu, x, o);
        if (lane >= o) x += y;
    }
    if (lane == 31) warpsums[wid] = x;
    __syncthreads();
    if (wid == 0) {
        int s = warpsums[lane];
        #pragma unroll
        for (int o = 1; o < 32; o <<= 1) {
            int y = __shfl_up_sync(0xffffffffu, s, o);
            if (lane >= o) s += y;
        }
        warpsums[lane] = s;
    }
    __syncthreads();
    int pref = (wid > 0) ? warpsums[wid - 1] : 0;
    int incl = x + pref;
    if (i < n) g_rowptr[i] = incl - v;
    if (tid == SCAN_BLK - 1) g_blksum[blockIdx.x] = incl;
}

__global__ void scan_partials_kernel(int nb, int n) {
    __shared__ int warpsums[4];
    int tid = threadIdx.x, lane = tid & 31, wid = tid >> 5;
    int v = (tid < nb) ? g_blksum[tid] : 0;
    int x = v;
    #pragma unroll
    for (int o = 1; o < 32; o <<= 1) {
        int y = __shfl_up_sync(0xffffffffu, x, o);
        if (lane >= o) x += y;
    }
    if (lane == 31) warpsums[wid] = x;
    __syncthreads();
    if (tid == 0) {
        int c = 0;
        #pragma unroll
        for (int q = 0; q < 4; q++) { int t = warpsums[q]; warpsums[q] = c; c += t; }
    }
    __syncthreads();
    int incl = x + warpsums[wid];
    if (tid < nb) g_blksum[tid] = incl - v;
    if (tid == nb - 1) g_rowptr[n] = incl;
}

// Adds block offsets AND materializes the mutable scatter cursor copy.
__global__ void scan_add_kernel(int n) {
    int i = blockIdx.x * SCAN_BLK + threadIdx.x;
    if (i < n) {
        int v = g_rowptr[i] + g_blksum[blockIdx.x];
        g_rowptr[i]  = v;
        g_rowptr2[i] = v;
    }
}

// Single atomic per edge: cursor atomicAdd yields the slot directly.
__global__ void scatter_kernel(const int* __restrict__ rows,
                               const int* __restrict__ cols,
                               const float* __restrict__ vals, int E) {
    int i = blockIdx.x * blockDim.x + threadIdx.x;
    if (i < E) {
        int p = atomicAdd(&g_rowptr2[rows[i]], 1);
        g_epack[p] = make_int2(cols[i], __float_as_int(vals[i]));
    }
}

// ---------------- Tensor-core GEMM via fp16 mma.sync ----------------
// C[M,BN] = A[M,K] * W[BN,K]^T, 2-term fp16 split: D += Ah*Bh + Ah*Bl.
// AHALF: A already fp16 (straight copy into smem).
// BHALF: W pre-split fp16 hi/lo planes (straight copies into smem).
// K-chunk = 64 -> 128B fp16 rows, SW128 swizzle, double-buffered. fp16 out.
template <int BM, int BN, int WM, int WN, int K, bool AHALF, bool BHALF>
__global__ void __launch_bounds__(WM * WN * 32, 2)
mma_gemm_kernel(const void* __restrict__ Av, const void* __restrict__ Wv,
                const __half* __restrict__ Wlo2, __half* __restrict__ C, int M)
{
    constexpr int THREADS = WM * WN * 32;
    constexpr int NCHUNK  = K / 64;
    constexpr int ASZ = BM * 128;
    constexpr int BSZ = BN * 128;
    constexpr int BUF = ASZ + 2 * BSZ;
    constexpr int ALF = BM * 16 / THREADS;       // float4 loads (fp32 A)
    constexpr int ALH = BM * 8 / THREADS;        // uint4 loads (fp16 A)
    constexpr int BLF = BN * 16 / THREADS;       // float4 loads (fp32 W)
    constexpr int BLH = BN * 8 / THREADS;        // uint4 loads per fp16 W plane
    constexpr int MT  = BM / WM / 16;
    constexpr int NT  = BN / WN / 8;

    extern __shared__ __align__(1024) char smem[];
    const uint32_t sb = smem_u32(smem);

    const int tid = threadIdx.x;
    const int l   = tid & 31;
    const int w   = tid >> 5;
    const int wmBase = (w % WM) * (BM / WM);
    const int wnBase = (w / WM) * (BN / WN);
    const int m0 = blockIdx.x * BM;

    const float*  Af = (const float*)Av;
    const __half* Ah = (const __half*)Av;
    const float*  Wf  = (const float*)Wv;
    const __half* Whi = (const __half*)Wv;

    float acc[MT][NT][4];
    #pragma unroll
    for (int i = 0; i < MT; i++)
        #pragma unroll
        for (int j = 0; j < NT; j++)
            #pragma unroll
            for (int q = 0; q < 4; q++) acc[i][j][q] = 0.f;

    uint2 regAh[AHALF ? 1 : ALF];
    uint4 regAp[AHALF ? ALH : 1];
    uint2 regBh[BHALF ? 1 : BLF], regBl[BHALF ? 1 : BLF];
    uint4 regBph[BHALF ? BLH : 1], regBpl[BHALF ? BLH : 1];

    const int arow = l & 15;
    const int acol = (l & 16) ? 16 : 0;
    const int brow = ((l & 16) ? 8 : 0) + (l & 7);
    const int bcol = (l & 8) ? 16 : 0;

    auto loadChunk = [&](int c) {
        const int k0 = c * 64;
        if constexpr (AHALF) {
            #pragma unroll
            for (int i = 0; i < ALH; i++) {
                int idx = tid + i * THREADS;
                int r = idx >> 3, u = idx & 7;
                int row = m0 + r; if (row >= M) row = M - 1;
                regAp[i] = __ldg((const uint4*)(Ah + (size_t)row * K + k0) + u);
            }
        } else {
            #pragma unroll
            for (int i = 0; i < ALF; i++) {
                int idx = tid + i * THREADS;
                int r = idx >> 4, c4 = (idx & 15) << 2;
                int row = m0 + r; if (row >= M) row = M - 1;
                float4 v = __ldg((const float4*)(Af + (size_t)row * K + k0 + c4));
                regAh[i] = cvt_hi(v);
            }
        }
        if constexpr (BHALF) {
            #pragma unroll
            for (int i = 0; i < BLH; i++) {
                int idx = tid + i * THREADS;
                int r = idx >> 3, u = idx & 7;
                size_t off = (size_t)r * K + k0 + u * 8;
                regBph[i] = __ldg((const uint4*)(Whi + off));
                regBpl[i] = __ldg((const uint4*)(Wlo2 + off));
            }
        } else {
            #pragma unroll
            for (int i = 0; i < BLF; i++) {
                int idx = tid + i * THREADS;
                int r = idx >> 4, c4 = (idx & 15) << 2;
                float4 v = __ldg((const float4*)(Wf + (size_t)r * K + k0 + c4));
                regBh[i] = cvt_hi(v);
                regBl[i] = cvt_lo(v, regBh[i]);
            }
        }
    };

    auto stsChunk = [&](int b) {
        char* base = smem + b * BUF;
        char* aHi  = base;
        char* bHi  = base + ASZ;
        char* bLo  = bHi + BSZ;
        if constexpr (AHALF) {
            #pragma unroll
            for (int i = 0; i < ALH; i++) {
                int idx = tid + i * THREADS;
                int r = idx >> 3, u = idx & 7;
                *(uint4*)(aHi + sw128((uint32_t)(r * 128 + u * 16))) = regAp[i];
            }
        } else {
            #pragma unroll
            for (int i = 0; i < ALF; i++) {
                int idx = tid + i * THREADS;
                int r = idx >> 4, c4 = (idx & 15) << 2;
                *(uint2*)(aHi + sw128((uint32_t)(r * 128 + c4 * 2))) = regAh[i];
            }
        }
        if constexpr (BHALF) {
            #pragma unroll
            for (int i = 0; i < BLH; i++) {
                int idx = tid + i * THREADS;
                int r = idx >> 3, u = idx & 7;
                uint32_t off = sw128((uint32_t)(r * 128 + u * 16));
                *(uint4*)(bHi + off) = regBph[i];
                *(uint4*)(bLo + off) = regBpl[i];
            }
        } else {
            #pragma unroll
            for (int i = 0; i < BLF; i++) {
                int idx = tid + i * THREADS;
                int r = idx >> 4, c4 = (idx & 15) << 2;
                uint32_t off = sw128((uint32_t)(r * 128 + c4 * 2));
                *(uint2*)(bHi + off) = regBh[i];
                *(uint2*)(bLo + off) = regBl[i];
            }
        }
    };

    auto compute = [&](int b) {
        const uint32_t sAhi = sb + b * BUF;
        const uint32_t sBhi = sAhi + ASZ;
        const uint32_t sBlo = sBhi + BSZ;
        #pragma unroll
        for (int kb = 0; kb < 4; kb++) {
            const int kboff = kb * 32;
            uint32_t aH[MT][4];
            #pragma unroll
            for (int mt = 0; mt < MT; mt++) {
                uint32_t rowb = (uint32_t)((wmBase + mt * 16 + arow) * 128);
                ldsm_x4(aH[mt], sAhi + sw128(rowb + kboff + acol));
            }
            uint32_t bH[NT][2], bLo[NT][2];
            #pragma unroll
            for (int nt = 0; nt < NT; nt += 2) {
                uint32_t rowb = (uint32_t)((wnBase + nt * 8 + brow) * 128);
                uint32_t t[4];
                ldsm_x4(t, sBhi + sw128(rowb + kboff + bcol));
                bH[nt][0] = t[0]; bH[nt][1] = t[1];
                bH[nt + 1][0] = t[2]; bH[nt + 1][1] = t[3];
                ldsm_x4(t, sBlo + sw128(rowb + kboff + bcol));
                bLo[nt][0] = t[0]; bLo[nt][1] = t[1];
                bLo[nt + 1][0] = t[2]; bLo[nt + 1][1] = t[3];
            }
            #pragma unroll
            for (int mt = 0; mt < MT; mt++)
                #pragma unroll
                for (int nt = 0; nt < NT; nt++) {
                    mma16816(acc[mt][nt], aH[mt], bH[nt]);
                    mma16816(acc[mt][nt], aH[mt], bLo[nt]);
                }
        }
    };

    loadChunk(0);
    stsChunk(0);
    __syncthreads();

    for (int c = 0; c < NCHUNK; c++) {
        if (c + 1 < NCHUNK) loadChunk(c + 1);
        compute(c & 1);
        if (c + 1 < NCHUNK) {
            __syncthreads();
            stsChunk((c + 1) & 1);
            __syncthreads();
        }
    }

    #pragma unroll
    for (int mt = 0; mt < MT; mt++) {
        int m = m0 + wmBase + mt * 16 + (l >> 2);
        #pragma unroll
        for (int nt = 0; nt < NT; nt++) {
            int nn = wnBase + nt * 8 + ((l & 3) << 1);
            if (m < M)
                *(__half2*)(C + (size_t)m * BN + nn) =
                    __floats2half2_rn(acc[mt][nt][0], acc[mt][nt][1]);
            if (m + 8 < M)
                *(__half2*)(C + (size_t)(m + 8) * BN + nn) =
                    __floats2half2_rn(acc[mt][nt][2], acc[mt][nt][3]);
        }
    }
}

// ---------------- SpMM (CSR, warp per row, fp16 gather, 2x unroll) ---------
// h fp16, accumulate fp32. OUTHALF: store fp16, else fp32.
template <int WIDTH, bool RELU, bool OUTHALF>
__global__ void spmm_kernel(const __half* __restrict__ h,
                            void* __restrict__ outv, int n) {
    int warp = (blockIdx.x * blockDim.x + threadIdx.x) >> 5;
    int lane = threadIdx.x & 31;
    if (warp >= n) return;
    int s = g_rowptr[warp];
    int e = g_rowptr[warp + 1];

    if (WIDTH == 128) {
        float4 acc = make_float4(0.f, 0.f, 0.f, 0.f);
        int i = s;
        for (; i + 2 <= e; i += 2) {
            int2 p0 = g_epack[i];
            int2 p1 = g_epack[i + 1];
            float v0 = __int_as_float(p0.y);
            float v1 = __int_as_float(p1.y);
            uint2 r0 = __ldg((const uint2*)(h + (size_t)p0.x * 128) + lane);
            uint2 r1 = __ldg((const uint2*)(h + (size_t)p1.x * 128) + lane);
            float2 a01 = __half22float2(*(__half2*)&r0.x);
            float2 a23 = __half22float2(*(__half2*)&r0.y);
            float2 b01 = __half22float2(*(__half2*)&r1.x);
            float2 b23 = __half22float2(*(__half2*)&r1.y);
            acc.x += v0 * a01.x; acc.y += v0 * a01.y;
            acc.z += v0 * a23.x; acc.w += v0 * a23.y;
            acc.x += v1 * b01.x; acc.y += v1 * b01.y;
            acc.z += v1 * b23.x; acc.w += v1 * b23.y;
        }
        if (i < e) {
            int2 p = g_epack[i];
            float v = __int_as_float(p.y);
            uint2 r0 = __ldg((const uint2*)(h + (size_t)p.x * 128) + lane);
            float2 a01 = __half22float2(*(__half2*)&r0.x);
            float2 a23 = __half22float2(*(__half2*)&r0.y);
            acc.x += v * a01.x; acc.y += v * a01.y;
            acc.z += v * a23.x; acc.w += v * a23.y;
        }
        if (RELU) {
            acc.x = fmaxf(acc.x, 0.f); acc.y = fmaxf(acc.y, 0.f);
            acc.z = fmaxf(acc.z, 0.f); acc.w = fmaxf(acc.w, 0.f);
        }
        if constexpr (OUTHALF) {
            __half2 o01 = __floats2half2_rn(acc.x, acc.y);
            __half2 o23 = __floats2half2_rn(acc.z, acc.w);
            ((uint2*)((__half*)outv + (size_t)warp * 128))[lane] =
                make_uint2(*(uint32_t*)&o01, *(uint32_t*)&o23);
        } else {
            ((float4*)((float*)outv + (size_t)warp * 128))[lane] = acc;
        }
    } else {  // WIDTH == 64
        float2 acc = make_float2(0.f, 0.f);
        int i = s;
        for (; i + 2 <= e; i += 2) {
            int2 p0 = g_epack[i];
            int2 p1 = g_epack[i + 1];
            float v0 = __int_as_float(p0.y);
            float v1 = __int_as_float(p1.y);
            uint32_t r0 = __ldg((const uint32_t*)(h + (size_t)p0.x * 64) + lane);
            uint32_t r1 = __ldg((const uint32_t*)(h + (size_t)p1.x * 64) + lane);
            float2 a = __half22float2(*(__half2*)&r0);
            float2 b = __half22float2(*(__half2*)&r1);
            acc.x += v0 * a.x; acc.y += v0 * a.y;
            acc.x += v1 * b.x; acc.y += v1 * b.y;
        }
        if (i < e) {
            int2 p = g_epack[i];
            float v = __int_as_float(p.y);
            uint32_t r0 = __ldg((const uint32_t*)(h + (size_t)p.x * 64) + lane);
            float2 a = __half22float2(*(__half2*)&r0);
            acc.x += v * a.x; acc.y += v * a.y;
        }
        if (RELU) { acc.x = fmaxf(acc.x, 0.f); acc.y = fmaxf(acc.y, 0.f); }
        ((float2*)((float*)outv + (size_t)warp * 64))[lane] = acc;
    }
}

// ---------------- Launcher ----------------
extern "C" void kernel_launch(void* const* d_in, const int* in_sizes, int n_in,
                              void* d_out, int out_size) {
    const float* x    = (const float*)d_in[0];
    const int*   rows = (const int*)  d_in[1];
    const int*   cols = (const int*)  d_in[2];
    const float* vals = (const float*)d_in[3];
    const float* W0   = (const float*)d_in[4];
    const float* W1   = (const float*)d_in[5];
    const float* W2   = (const float*)d_in[6];
    float* out = (float*)d_out;

    int n = in_sizes[0] / DIM_IN;   // 100000
    int E = in_sizes[1];            // 1600000
    int nb = (n + SCAN_BLK - 1) / SCAN_BLK;

    float* bufA; float* bufB;
    __half *whi, *wlo;
    cudaGetSymbolAddress((void**)&bufA, g_bufA);
    cudaGetSymbolAddress((void**)&bufB, g_bufB);
    cudaGetSymbolAddress((void**)&whi, g_Whi);
    cudaGetSymbolAddress((void**)&wlo, g_Wlo);
    __half* bufAh = (__half*)bufA;
    __half* bufBh = (__half*)bufB;

    const int smemG0 = 2 * 48 * 1024;
    const int smemG2 = 2 * 32 * 1024;
    cudaFuncSetAttribute(mma_gemm_kernel<128, 128, 2, 4, 512, false, false>,
                         cudaFuncAttributeMaxDynamicSharedMemorySize, smemG0);
    cudaFuncSetAttribute(mma_gemm_kernel<128, 128, 2, 4, 128, true, true>,
                         cudaFuncAttributeMaxDynamicSharedMemorySize, smemG0);
    cudaFuncSetAttribute(mma_gemm_kernel<128, 64, 4, 2, 128, true, true>,
                         cudaFuncAttributeMaxDynamicSharedMemorySize, smemG2);

    // ---- W1/W2 pre-split (tiny, independent) ----
    convert_w_kernel<<<(W12_TOTAL + 255) / 256, 256>>>(W1, W2);

    // ---- CSR build (multi-block scan, single-atomic scatter) ----
    zero_deg_kernel<<<(n + 255) / 256, 256>>>(n);
    hist_kernel<<<(E + 255) / 256, 256>>>(rows, E);
    scan_blocks_kernel<<<nb, SCAN_BLK>>>(n);
    scan_partials_kernel<<<1, 128>>>(nb, n);
    scan_add_kernel<<<nb, SCAN_BLK>>>(n);
    scatter_kernel<<<(E + 255) / 256, 256>>>(rows, cols, vals, E);

    int gemmGrid = (n + 127) / 128;
    int spmmGrid = (n + 7) / 8;

    // layer 0: x(fp32) @ W0^T -> fp16; spmm fp16->fp16 + relu
    mma_gemm_kernel<128, 128, 2, 4, 512, false, false><<<gemmGrid, 256, smemG0>>>(
        x, W0, nullptr, bufAh, n);
    spmm_kernel<128, true, true><<<spmmGrid, 256>>>(bufAh, bufBh, n);

    // layer 1: h(fp16) @ W1^T -> fp16 (pre-split W); spmm fp16->fp16 + relu
    mma_gemm_kernel<128, 128, 2, 4, 128, true, true><<<gemmGrid, 256, smemG0>>>(
        bufBh, whi, wlo, bufAh, n);
    spmm_kernel<128, true, true><<<spmmGrid, 256>>>(bufAh, bufBh, n);

    // layer 2: h(fp16) @ W2^T -> fp16 (pre-split W); spmm fp16->fp32 (no relu)
    mma_gemm_kernel<128, 64, 4, 2, 128, true, true><<<gemmGrid, 256, smemG2>>>(
        bufBh, whi + W1_ELEMS, wlo + W1_ELEMS, bufAh, n);
    spmm_kernel<64, false, false><<<spmmGrid, 256>>>(bufAh, out, n);
}